// round 2
// baseline (speedup 1.0000x reference)
#include <cuda_runtime.h>

#define N_NODES 50000
#define N_EDGES 800000
#define DIM 128
#define NL 3

// Scratch (allocation-free rule: __device__ globals)
__device__ float g_h[(size_t)N_NODES * DIM];   // h = z + neighbor sum
__device__ float g_t[(size_t)N_NODES * DIM];   // t = relu(h@W1 + b1)
__device__ float g_z[(size_t)N_NODES * DIM];   // z = relu(t@W2 + b2)
__device__ int   g_is64;

// ---------------------------------------------------------------------------
// Detect whether edge_index is int64 or int32 (JAX x64-disabled demotes it).
// Values are in [0, 50000): if int64, every high 32-bit word is 0.
// Deterministic (data-dependent only), graph-capturable.
// ---------------------------------------------------------------------------
__global__ void detect_idx_kernel(const int* __restrict__ ei_i32) {
    if (threadIdx.x == 0 && blockIdx.x == 0) {
        int is64 = 1;
        for (int i = 0; i < 64; i++) {
            if (ei_i32[2 * i + 1] != 0) { is64 = 0; break; }
        }
        g_is64 = is64;
    }
}

// h = z  (the (1+eps)*z_i term, eps=0)
__global__ void copy_kernel(const float4* __restrict__ src, float4* __restrict__ dst, int n4) {
    int i = blockIdx.x * blockDim.x + threadIdx.x;
    int stride = gridDim.x * blockDim.x;
    for (; i < n4; i += stride) dst[i] = src[i];
}

// ---------------------------------------------------------------------------
// Edge scatter: one warp per edge; each lane moves a float4 (lane*4 dims).
// z fits in L2 (25.6MB), so gather + vector reductions are L2-resident.
// ---------------------------------------------------------------------------
__global__ void scatter_kernel(const void* __restrict__ ei,
                               const float* __restrict__ z,
                               float* __restrict__ h) {
    int idx = blockIdx.x * blockDim.x + threadIdx.x;
    int e = idx >> 5;
    if (e >= N_EDGES) return;
    int lane = idx & 31;

    long long s, d;
    if (g_is64) {
        const long long* p = (const long long*)ei;
        s = p[e];
        d = p[N_EDGES + e];
    } else {
        const int* p = (const int*)ei;
        s = p[e];
        d = p[N_EDGES + e];
    }

    const float4 v = *(const float4*)(z + (size_t)s * DIM + lane * 4);
    float* out = h + (size_t)d * DIM + lane * 4;
    asm volatile("red.global.add.v4.f32 [%0], {%1, %2, %3, %4};"
                 :: "l"(out), "f"(v.x), "f"(v.y), "f"(v.z), "f"(v.w)
                 : "memory");
}

// ---------------------------------------------------------------------------
// C[m, n] = relu( A[m, :] @ W[:, n] + bias[n] ),  M=50000, N=K=128.
// Tile: BM=128, full K and N resident in smem (64KB A + 64KB W).
// 256 threads, each computes an 8x8 microtile. A-reads are 2-address
// broadcasts (bank-safe), W-reads are contiguous float4.
// ---------------------------------------------------------------------------
__global__ void gemm_bias_relu(const float* __restrict__ A,
                               const float* __restrict__ W,
                               const float* __restrict__ bias,
                               float* __restrict__ C) {
    extern __shared__ float smem[];
    float* sA = smem;              // [128][128]
    float* sW = smem + DIM * 128;  // [128][128]

    const int tid = threadIdx.x;           // 256 threads
    const int m0  = blockIdx.x * 128;

    // Load W (16384 floats) as float4, fully coalesced.
    {
        const float4* src = (const float4*)W;
        float4* dst = (float4*)sW;
        for (int i = tid; i < DIM * DIM / 4; i += 256) dst[i] = src[i];
    }
    // Load A tile: lane kv covers k-chunk, row-major store (no conflicts).
    {
        const int kv = (tid & 31) * 4;
        for (int mi = tid >> 5; mi < 128; mi += 8) {
            const int m = m0 + mi;
            float4 v = make_float4(0.f, 0.f, 0.f, 0.f);
            if (m < N_NODES) v = *(const float4*)(A + (size_t)m * DIM + kv);
            *(float4*)(sA + mi * DIM + kv) = v;
        }
    }
    __syncthreads();

    const int tx = tid & 15;   // column group: 8 cols at tx*8
    const int ty = tid >> 4;   // row group:    8 rows at ty*8

    float acc[8][8];
#pragma unroll
    for (int i = 0; i < 8; i++)
#pragma unroll
        for (int j = 0; j < 8; j++) acc[i][j] = 0.f;

#pragma unroll 4
    for (int k = 0; k < DIM; k++) {
        float b[8];
        {
            float4 b0 = *(const float4*)(sW + k * DIM + tx * 8);
            float4 b1 = *(const float4*)(sW + k * DIM + tx * 8 + 4);
            b[0] = b0.x; b[1] = b0.y; b[2] = b0.z; b[3] = b0.w;
            b[4] = b1.x; b[5] = b1.y; b[6] = b1.z; b[7] = b1.w;
        }
        float a[8];
#pragma unroll
        for (int i = 0; i < 8; i++) a[i] = sA[(ty * 8 + i) * DIM + k];
#pragma unroll
        for (int i = 0; i < 8; i++)
#pragma unroll
            for (int j = 0; j < 8; j++) acc[i][j] = fmaf(a[i], b[j], acc[i][j]);
    }

    float bv[8];
    {
        float4 b0 = *(const float4*)(bias + tx * 8);
        float4 b1 = *(const float4*)(bias + tx * 8 + 4);
        bv[0] = b0.x; bv[1] = b0.y; bv[2] = b0.z; bv[3] = b0.w;
        bv[4] = b1.x; bv[5] = b1.y; bv[6] = b1.z; bv[7] = b1.w;
    }

#pragma unroll
    for (int i = 0; i < 8; i++) {
        const int m = m0 + ty * 8 + i;
        if (m < N_NODES) {
            float4 o0, o1;
            o0.x = fmaxf(acc[i][0] + bv[0], 0.f);
            o0.y = fmaxf(acc[i][1] + bv[1], 0.f);
            o0.z = fmaxf(acc[i][2] + bv[2], 0.f);
            o0.w = fmaxf(acc[i][3] + bv[3], 0.f);
            o1.x = fmaxf(acc[i][4] + bv[4], 0.f);
            o1.y = fmaxf(acc[i][5] + bv[5], 0.f);
            o1.z = fmaxf(acc[i][6] + bv[6], 0.f);
            o1.w = fmaxf(acc[i][7] + bv[7], 0.f);
            *(float4*)(C + (size_t)m * DIM + tx * 8)     = o0;
            *(float4*)(C + (size_t)m * DIM + tx * 8 + 4) = o1;
        }
    }
}

extern "C" void kernel_launch(void* const* d_in, const int* in_sizes, int n_in,
                              void* d_out, int out_size) {
    const float* x   = (const float*)d_in[0];
    const float* Ws1 = (const float*)d_in[1];
    const float* bs1 = (const float*)d_in[2];
    const float* Ws2 = (const float*)d_in[3];
    const float* bs2 = (const float*)d_in[4];
    const void*  ei  = d_in[5];
    float* out = (float*)d_out;

    const int SMEM_GEMM = 2 * DIM * 128 * (int)sizeof(float);  // 128 KB
    cudaFuncSetAttribute(gemm_bias_relu,
                         cudaFuncAttributeMaxDynamicSharedMemorySize, SMEM_GEMM);

    float *h_buf, *t_buf, *z_buf;
    cudaGetSymbolAddress((void**)&h_buf, g_h);
    cudaGetSymbolAddress((void**)&t_buf, g_t);
    cudaGetSymbolAddress((void**)&z_buf, g_z);

    detect_idx_kernel<<<1, 32>>>((const int*)ei);

    const int n4 = N_NODES * DIM / 4;                       // 1.6M float4
    const int copy_blocks = 4096;
    const int scat_blocks = (N_EDGES * 32 + 255) / 256;     // 100000
    const int gemm_blocks = (N_NODES + 127) / 128;          // 391

    const float* zcur = x;
    for (int l = 0; l < NL; l++) {
        copy_kernel<<<copy_blocks, 256>>>((const float4*)zcur, (float4*)h_buf, n4);
        scatter_kernel<<<scat_blocks, 256>>>(ei, zcur, h_buf);
        gemm_bias_relu<<<gemm_blocks, 256, SMEM_GEMM>>>(
            h_buf, Ws1 + (size_t)l * DIM * DIM, bs1 + (size_t)l * DIM, t_buf);
        float* zout = (l == NL - 1) ? out : z_buf;
        gemm_bias_relu<<<gemm_blocks, 256, SMEM_GEMM>>>(
            t_buf, Ws2 + (size_t)l * DIM * DIM, bs2 + (size_t)l * DIM, zout);
        zcur = zout;
    }
}

// round 4
// speedup vs baseline: 1.8239x; 1.8239x over previous
#include <cuda_runtime.h>

#define N_NODES 50000
#define N_EDGES 800000
#define DIM 128
#define NL 3

// Scratch (allocation-free rule: __device__ globals)
__device__ float g_h[(size_t)N_NODES * DIM];   // h = z + neighbor sum
__device__ float g_t[(size_t)N_NODES * DIM];   // t = relu(h@W1 + b1)
__device__ float g_z[(size_t)N_NODES * DIM];   // z = relu(t@W2 + b2)
__device__ int   g_is64;

// ---------------------------------------------------------------------------
// Detect whether edge_index is int64 or int32 (JAX x64-disabled demotes it).
// Values are in [0, 50000): if int64, every high 32-bit word is 0.
// ---------------------------------------------------------------------------
__global__ void detect_idx_kernel(const int* __restrict__ ei_i32) {
    if (threadIdx.x == 0 && blockIdx.x == 0) {
        int is64 = 1;
        for (int i = 0; i < 64; i++) {
            if (ei_i32[2 * i + 1] != 0) { is64 = 0; break; }
        }
        g_is64 = is64;
    }
}

// h = z  (the (1+eps)*z_i term, eps=0)
__global__ void copy_kernel(const float4* __restrict__ src, float4* __restrict__ dst, int n4) {
    int i = blockIdx.x * blockDim.x + threadIdx.x;
    int stride = gridDim.x * blockDim.x;
    for (; i < n4; i += stride) dst[i] = src[i];
}

// ---------------------------------------------------------------------------
// Edge scatter: one warp per edge; each lane moves a float4 (lane*4 dims).
// z fits in L2 (25.6MB), so gather + vector reductions are L2-resident.
// ---------------------------------------------------------------------------
__global__ void scatter_kernel(const void* __restrict__ ei,
                               const float* __restrict__ z,
                               float* __restrict__ h) {
    int idx = blockIdx.x * blockDim.x + threadIdx.x;
    int e = idx >> 5;
    if (e >= N_EDGES) return;
    int lane = idx & 31;

    long long s, d;
    if (g_is64) {
        const long long* p = (const long long*)ei;
        s = p[e];
        d = p[N_EDGES + e];
    } else {
        const int* p = (const int*)ei;
        s = p[e];
        d = p[N_EDGES + e];
    }

    const float4 v = *(const float4*)(z + (size_t)s * DIM + lane * 4);
    float* out = h + (size_t)d * DIM + lane * 4;
    asm volatile("red.global.add.v4.f32 [%0], {%1, %2, %3, %4};"
                 :: "l"(out), "f"(v.x), "f"(v.y), "f"(v.z), "f"(v.w)
                 : "memory");
}

// ---------------------------------------------------------------------------
// C[m, n] = relu( A[m, :] @ W[:, n] + bias[n] ),  M=50000, N=K=128.
// 128x128 tile, full K in smem. 512 threads, 8x4 microtile:
//   tx = tid&31 -> 4 cols at tx*4   (W read: one LDS.128, 512B contiguous,
//                                    conflict-free; C store coalesced)
//   ty = tid>>5 -> 8 rows at ty*8   (A read: full-warp broadcast, 1 addr/warp)
// 16 warps/SM (vs 8 before) to cover LDS/FFMA latency.
// ---------------------------------------------------------------------------
__global__ __launch_bounds__(512, 1)
void gemm_bias_relu(const float* __restrict__ A,
                    const float* __restrict__ W,
                    const float* __restrict__ bias,
                    float* __restrict__ C) {
    extern __shared__ float smem[];
    float* sA = smem;              // [128][128]
    float* sW = smem + DIM * 128;  // [128][128]

    const int tid = threadIdx.x;   // 512 threads
    const int m0  = blockIdx.x * 128;

    // Load W (16384 floats) as float4, fully coalesced: 8 iters.
    {
        const float4* src = (const float4*)W;
        float4* dst = (float4*)sW;
#pragma unroll
        for (int i = 0; i < 8; i++) dst[tid + i * 512] = src[tid + i * 512];
    }
    // Load A tile: lane kv covers k-chunk, row-major store (no conflicts).
    {
        const int kv = (tid & 31) * 4;
#pragma unroll
        for (int r = 0; r < 8; r++) {
            const int mi = (tid >> 5) + r * 16;
            const int m = m0 + mi;
            float4 v = make_float4(0.f, 0.f, 0.f, 0.f);
            if (m < N_NODES) v = *(const float4*)(A + (size_t)m * DIM + kv);
            *(float4*)(sA + mi * DIM + kv) = v;
        }
    }
    __syncthreads();

    const int tx = tid & 31;   // 4 cols at tx*4
    const int ty = tid >> 5;   // 8 rows at ty*8

    float acc[8][4];
#pragma unroll
    for (int i = 0; i < 8; i++)
#pragma unroll
        for (int j = 0; j < 4; j++) acc[i][j] = 0.f;

    const float* sArow = sA + ty * 8 * DIM;
    const float* sWcol = sW + tx * 4;

#pragma unroll 4
    for (int k = 0; k < DIM; k++) {
        const float4 b4 = *(const float4*)(sWcol + k * DIM);
        float a[8];
#pragma unroll
        for (int i = 0; i < 8; i++) a[i] = sArow[i * DIM + k];
#pragma unroll
        for (int i = 0; i < 8; i++) {
            acc[i][0] = fmaf(a[i], b4.x, acc[i][0]);
            acc[i][1] = fmaf(a[i], b4.y, acc[i][1]);
            acc[i][2] = fmaf(a[i], b4.z, acc[i][2]);
            acc[i][3] = fmaf(a[i], b4.w, acc[i][3]);
        }
    }

    const float4 bv = *(const float4*)(bias + tx * 4);

#pragma unroll
    for (int i = 0; i < 8; i++) {
        const int m = m0 + ty * 8 + i;
        if (m < N_NODES) {
            float4 o;
            o.x = fmaxf(acc[i][0] + bv.x, 0.f);
            o.y = fmaxf(acc[i][1] + bv.y, 0.f);
            o.z = fmaxf(acc[i][2] + bv.z, 0.f);
            o.w = fmaxf(acc[i][3] + bv.w, 0.f);
            *(float4*)(C + (size_t)m * DIM + tx * 4) = o;
        }
    }
}

extern "C" void kernel_launch(void* const* d_in, const int* in_sizes, int n_in,
                              void* d_out, int out_size) {
    const float* x   = (const float*)d_in[0];
    const float* Ws1 = (const float*)d_in[1];
    const float* bs1 = (const float*)d_in[2];
    const float* Ws2 = (const float*)d_in[3];
    const float* bs2 = (const float*)d_in[4];
    const void*  ei  = d_in[5];
    float* out = (float*)d_out;

    const int SMEM_GEMM = 2 * DIM * 128 * (int)sizeof(float);  // 128 KB
    cudaFuncSetAttribute(gemm_bias_relu,
                         cudaFuncAttributeMaxDynamicSharedMemorySize, SMEM_GEMM);

    float *h_buf, *t_buf, *z_buf;
    cudaGetSymbolAddress((void**)&h_buf, g_h);
    cudaGetSymbolAddress((void**)&t_buf, g_t);
    cudaGetSymbolAddress((void**)&z_buf, g_z);

    detect_idx_kernel<<<1, 32>>>((const int*)ei);

    const int n4 = N_NODES * DIM / 4;                       // 1.6M float4
    const int copy_blocks = 4096;
    const int scat_blocks = (N_EDGES * 32 + 255) / 256;     // 100000
    const int gemm_blocks = (N_NODES + 127) / 128;          // 391

    const float* zcur = x;
    for (int l = 0; l < NL; l++) {
        copy_kernel<<<copy_blocks, 256>>>((const float4*)zcur, (float4*)h_buf, n4);
        scatter_kernel<<<scat_blocks, 256>>>(ei, zcur, h_buf);
        gemm_bias_relu<<<gemm_blocks, 512, SMEM_GEMM>>>(
            h_buf, Ws1 + (size_t)l * DIM * DIM, bs1 + (size_t)l * DIM, t_buf);
        float* zout = (l == NL - 1) ? out : z_buf;
        gemm_bias_relu<<<gemm_blocks, 512, SMEM_GEMM>>>(
            t_buf, Ws2 + (size_t)l * DIM * DIM, bs2 + (size_t)l * DIM, zout);
        zcur = zout;
    }
}